// round 14
// baseline (speedup 1.0000x reference)
#include <cuda_runtime.h>
#include <cuda_bf16.h>
#include <math_constants.h>
#include <cstdint>

// KCRouteEncoder:
//   out = pooled_cid + bias + (pooled_content @ W)     (alphas sum to 1)
// Serialized pool -> gemm (overlap measured harmful 3x; tcgen05 unavailable:
// harness PTX target is sm_103 which rejects tcgen05.*).
// K1 pool (R5 best, W-convert folded into first 768 blocks).
// K2 gemm v9: BM=128 x BN=128 x BK=64, XOR-swizzled smem, 3-stage cp.async,
//     2 CTAs/SM, grid (ceil(npos/128), 2) = 200 blocks (single wave).

#define KLEV   8
#define EMB    256
#define PDIM   768
#define MAXPOS 12800

#define BM 128
#define BN 128
#define BK 64
#define NCHUNK (PDIM / BK)                 // 12
#define NSTAGE 3
#define A_STG_B (BM * 128)                 // 16384 (128 rows x 128B)
#define W_STG_B (BK * 256)                 // 16384 (64 rows x 256B)
#define STG_B   (A_STG_B + W_STG_B)        // 32768
#define SMEM_TOTAL (NSTAGE * STG_B)        // 98304 -> 2 CTAs/SM

#define WCONV_BLOCKS (PDIM * EMB / 256)    // 768

__device__ __nv_bfloat16 g_P[(size_t)MAXPOS * PDIM];
__device__ __nv_bfloat16 g_W[(size_t)PDIM * EMB];

__device__ __forceinline__ uint32_t smem_u32(const void* p) {
    return (uint32_t)__cvta_generic_to_shared(p);
}
__device__ __forceinline__ void cp_async16(uint32_t dst, const void* src) {
    asm volatile("cp.async.cg.shared.global [%0], [%1], 16;\n" :: "r"(dst), "l"(src));
}
__device__ __forceinline__ void cp_commit() {
    asm volatile("cp.async.commit_group;\n");
}
template <int N>
__device__ __forceinline__ void cp_wait() {
    asm volatile("cp.async.wait_group %0;\n" :: "n"(N));
}

// ------------------------------------------------ fallback W convert (npos<768 only)
__global__ void convert_w_kernel(const float* __restrict__ proj_w) {
    int i = blockIdx.x * blockDim.x + threadIdx.x;
    if (i < PDIM * EMB)
        g_W[i] = __float2bfloat16_rn(__ldg(&proj_w[i]));
}

// ------------------------------------------------ K1: pool (identical to R5/R12)
__global__ void __launch_bounds__(256)
pool_kernel(const int* __restrict__ croutes,
            const float* __restrict__ cid_emb,
            const float* __restrict__ weight,
            const float* __restrict__ content_table,
            const float* __restrict__ proj_w,
            const float* __restrict__ proj_b,
            float* __restrict__ out,
            int npos)
{
    const int pos = blockIdx.x;
    const int t   = threadIdx.x;

    if (blockIdx.x < WCONV_BLOCKS) {
        int i = blockIdx.x * 256 + t;
        g_W[i] = __float2bfloat16_rn(__ldg(&proj_w[i]));
    }
    if (pos >= npos) return;

    __shared__ int   rels[KLEV];
    __shared__ float alph[KLEV];

    if (t < KLEV)
        rels[t] = croutes[(size_t)pos * KLEV + t] + 2;
    __syncthreads();

    if (t == 0) {
        float nw[KLEV];
        float m = -CUDART_INF_F;
#pragma unroll
        for (int k = 0; k < KLEV; k++) {
            nw[k] = (rels[k] != 0) ? __ldg(&weight[k]) : -CUDART_INF_F;
            m = fmaxf(m, nw[k]);
        }
        float s = 0.f, ex[KLEV];
#pragma unroll
        for (int k = 0; k < KLEV; k++) { ex[k] = expf(nw[k] - m); s += ex[k]; }
        float inv = 1.f / s;
#pragma unroll
        for (int k = 0; k < KLEV; k++) alph[k] = ex[k] * inv;
    }
    __syncthreads();

    float a[KLEV]; int r[KLEV];
#pragma unroll
    for (int k = 0; k < KLEV; k++) { a[k] = alph[k]; r[k] = rels[k]; }

    if (t < 192) {
        float4 s = make_float4(0.f, 0.f, 0.f, 0.f);
#pragma unroll
        for (int k = 0; k < KLEV; k++) {
            if (a[k] != 0.f) {
                float4 v = __ldg(((const float4*)content_table) + (size_t)r[k] * 192 + t);
                s.x = fmaf(a[k], v.x, s.x);
                s.y = fmaf(a[k], v.y, s.y);
                s.z = fmaf(a[k], v.z, s.z);
                s.w = fmaf(a[k], v.w, s.w);
            }
        }
        __nv_bfloat162 lo = __floats2bfloat162_rn(s.x, s.y);
        __nv_bfloat162 hi = __floats2bfloat162_rn(s.z, s.w);
        uint2 pk;
        pk.x = *reinterpret_cast<uint32_t*>(&lo);
        pk.y = *reinterpret_cast<uint32_t*>(&hi);
        *reinterpret_cast<uint2*>(g_P + (size_t)pos * PDIM + 4 * t) = pk;
    } else {
        int u = t - 192;
        float4 s = __ldg(((const float4*)proj_b) + u);
#pragma unroll
        for (int k = 0; k < KLEV; k++) {
            if (a[k] != 0.f && r[k] >= 2) {
                float4 v = __ldg(((const float4*)cid_emb) + (size_t)(r[k] - 2) * 64 + u);
                s.x = fmaf(a[k], v.x, s.x);
                s.y = fmaf(a[k], v.y, s.y);
                s.z = fmaf(a[k], v.z, s.z);
                s.w = fmaf(a[k], v.w, s.w);
            }
        }
        *reinterpret_cast<float4*>(out + (size_t)pos * EMB + 4 * u) = s;
    }
}

// ------------------------------------------------ K2: GEMM v9
// block (bx, by): rows [128bx,128bx+128), cols [128by,128by+128)
// 8 warps = 4(M) x 2(N): wm = warp&3 (32 rows), wn = warp>>2 (64 cols)
__global__ void __launch_bounds__(256, 2)
gemm_kernel(float* __restrict__ out, int npos)
{
    extern __shared__ __align__(16) char smem[];

    const int t    = threadIdx.x;
    const int warp = t >> 5;
    const int lane = t & 31;
    const int wm   = warp & 3;
    const int wn   = warp >> 2;
    const int blockRow = blockIdx.x * BM;
    const int nbase    = blockIdx.y * BN;

    float c[2][8][4];
#pragma unroll
    for (int mf = 0; mf < 2; mf++)
#pragma unroll
        for (int nf = 0; nf < 8; nf++)
#pragma unroll
            for (int i = 0; i < 4; i++) c[mf][nf][i] = 0.f;

    auto load_chunk = [&](int kc, int stg) {
        char* Ab = smem + stg * STG_B;
        char* Wb = Ab + A_STG_B;
        // A: 128 rows x 8 chunks of 16B = 1024; 4 per thread
#pragma unroll
        for (int i = 0; i < 4; i++) {
            int u   = t + i * 256;            // 0..1023
            int row = u >> 3, ch = u & 7;
            int gr  = blockRow + row; if (gr >= npos) gr = npos - 1;
            cp_async16(smem_u32(Ab + row * 128 + ((ch ^ (row & 7)) * 16)),
                       g_P + (size_t)gr * PDIM + kc * BK + ch * 8);
        }
        // W: 64 rows x 16 chunks of 16B = 1024; 4 per thread
#pragma unroll
        for (int i = 0; i < 4; i++) {
            int u  = t + i * 256;             // 0..1023
            int wr = u >> 4, wc = u & 15;     // row 0..63, chunk 0..15
            cp_async16(smem_u32(Wb + wr * 256 + ((wc ^ (wr & 7)) * 16)),
                       g_W + (size_t)(kc * BK + wr) * EMB + nbase + wc * 8);
        }
        cp_commit();
    };

    load_chunk(0, 0);
    load_chunk(1, 1);
    load_chunk(2, 2);

    int stg = 0;
    for (int kc = 0; kc < NCHUNK; kc++) {
        // outstanding: chunks kc .. min(kc+2, NCHUNK-1)
        if (kc + 2 < NCHUNK)      cp_wait<2>();
        else if (kc + 1 < NCHUNK) cp_wait<1>();
        else                      cp_wait<0>();
        __syncthreads();

        const char* As = smem + stg * STG_B;
        const char* Ws = As + A_STG_B;

#pragma unroll
        for (int ks = 0; ks < BK / 16; ks++) {
            uint32_t a[2][4];
#pragma unroll
            for (int mf = 0; mf < 2; mf++) {
                int row = wm * 32 + mf * 16 + (lane & 15);
                int ch  = ks * 2 + (lane >> 4);
                uint32_t addr = smem_u32(As + row * 128 + ((ch ^ (row & 7)) * 16));
                asm volatile("ldmatrix.sync.aligned.m8n8.x4.shared.b16 {%0,%1,%2,%3}, [%4];\n"
                             : "=r"(a[mf][0]), "=r"(a[mf][1]), "=r"(a[mf][2]), "=r"(a[mf][3])
                             : "r"(addr));
            }
            uint32_t b[8][2];
#pragma unroll
            for (int nf = 0; nf < 8; nf++) {
                int row = ks * 16 + (lane & 15);
                int ch  = wn * 8 + nf;        // 16B chunk = 8 bf16 cols
                uint32_t addr = smem_u32(Ws + row * 256 + ((ch ^ (row & 7)) * 16));
                asm volatile("ldmatrix.sync.aligned.m8n8.x2.trans.shared.b16 {%0,%1}, [%2];\n"
                             : "=r"(b[nf][0]), "=r"(b[nf][1]) : "r"(addr));
            }
#pragma unroll
            for (int mf = 0; mf < 2; mf++)
#pragma unroll
                for (int nf = 0; nf < 8; nf++) {
                    asm volatile(
                        "mma.sync.aligned.m16n8k16.row.col.f32.bf16.bf16.f32 "
                        "{%0,%1,%2,%3}, {%4,%5,%6,%7}, {%8,%9}, {%0,%1,%2,%3};\n"
                        : "+f"(c[mf][nf][0]), "+f"(c[mf][nf][1]),
                          "+f"(c[mf][nf][2]), "+f"(c[mf][nf][3])
                        : "r"(a[mf][0]), "r"(a[mf][1]), "r"(a[mf][2]), "r"(a[mf][3]),
                          "r"(b[nf][0]), "r"(b[nf][1]));
                }
        }
        __syncthreads();

        if (kc + NSTAGE < NCHUNK) load_chunk(kc + NSTAGE, stg);
        stg = (stg == NSTAGE - 1) ? 0 : stg + 1;
    }

    // epilogue: out += C
#pragma unroll
    for (int mf = 0; mf < 2; mf++) {
#pragma unroll
        for (int nf = 0; nf < 8; nf++) {
            int col  = nbase + wn * 64 + nf * 8 + (lane & 3) * 2;
            int row0 = blockRow + wm * 32 + mf * 16 + (lane >> 2);
            if (row0 < npos) {
                float2* o = reinterpret_cast<float2*>(&out[(size_t)row0 * EMB + col]);
                float2 v = *o;
                v.x += c[mf][nf][0]; v.y += c[mf][nf][1];
                *o = v;
            }
            int row1 = row0 + 8;
            if (row1 < npos) {
                float2* o = reinterpret_cast<float2*>(&out[(size_t)row1 * EMB + col]);
                float2 v = *o;
                v.x += c[mf][nf][2]; v.y += c[mf][nf][3];
                *o = v;
            }
        }
    }
}

// ------------------------------------------------ launch
extern "C" void kernel_launch(void* const* d_in, const int* in_sizes, int n_in,
                              void* d_out, int out_size)
{
    const int*   croutes       = (const int*)d_in[0];
    // d_in[1] = tailcs (unused)
    const float* cid_emb       = (const float*)d_in[2];
    const float* weight        = (const float*)d_in[3];
    const float* content_table = (const float*)d_in[4];
    const float* proj_w        = (const float*)d_in[5];
    const float* proj_b        = (const float*)d_in[6];
    float*       out           = (float*)d_out;

    int npos = in_sizes[0] / KLEV;
    if (npos > MAXPOS) npos = MAXPOS;

    if (npos < WCONV_BLOCKS)
        convert_w_kernel<<<(PDIM * EMB + 255) / 256, 256>>>(proj_w);

    pool_kernel<<<npos, 256>>>(croutes, cid_emb, weight, content_table,
                               proj_w, proj_b, out, npos);

    static bool attr_set = false;
    if (!attr_set) {
        cudaFuncSetAttribute(gemm_kernel,
                             cudaFuncAttributeMaxDynamicSharedMemorySize,
                             SMEM_TOTAL);
        attr_set = true;
    }
    dim3 grid((npos + BM - 1) / BM, 2);
    gemm_kernel<<<grid, 256, SMEM_TOTAL>>>(out, npos);
}

// round 15
// speedup vs baseline: 1.0893x; 1.0893x over previous
#include <cuda_runtime.h>
#include <cuda_bf16.h>
#include <math_constants.h>
#include <cstdint>

// KCRouteEncoder:
//   out = pooled_cid + bias + (pooled_content @ W)     (alphas sum to 1)
// Serialized pool -> gemm (overlap measured harmful 3x; tcgen05 rejected by
// the harness's sm_103 ptx target; BM bracketed 32/64/128 -> 64 optimal).
// K1 pool (R5 best, W-convert folded into first 768 blocks).
// K2 gemm v10: R12 config (BM=64 x BN=128 x BK=64, swizzled, 3-stage,
//     3 CTAs/SM, grid (200,2)) with SINGLE barrier per chunk: refill stage
//     (kc-1)%3 with chunk kc+2 right after the wait barrier.

#define KLEV   8
#define EMB    256
#define PDIM   768
#define MAXPOS 12800

#define BM 64
#define BN 128
#define BK 64
#define NCHUNK (PDIM / BK)                 // 12
#define NSTAGE 3
#define A_STG_B (BM * 128)                 // 8192  (64 rows x 128B)
#define W_STG_B (BK * 256)                 // 16384 (64 rows x 256B)
#define STG_B   (A_STG_B + W_STG_B)        // 24576
#define SMEM_TOTAL (NSTAGE * STG_B)        // 73728 -> 3 CTAs/SM

#define WCONV_BLOCKS (PDIM * EMB / 256)    // 768

__device__ __nv_bfloat16 g_P[(size_t)MAXPOS * PDIM];
__device__ __nv_bfloat16 g_W[(size_t)PDIM * EMB];

__device__ __forceinline__ uint32_t smem_u32(const void* p) {
    return (uint32_t)__cvta_generic_to_shared(p);
}
__device__ __forceinline__ void cp_async16(uint32_t dst, const void* src) {
    asm volatile("cp.async.cg.shared.global [%0], [%1], 16;\n" :: "r"(dst), "l"(src));
}
__device__ __forceinline__ void cp_commit() {
    asm volatile("cp.async.commit_group;\n");
}
template <int N>
__device__ __forceinline__ void cp_wait() {
    asm volatile("cp.async.wait_group %0;\n" :: "n"(N));
}

// ------------------------------------------------ fallback W convert (npos<768 only)
__global__ void convert_w_kernel(const float* __restrict__ proj_w) {
    int i = blockIdx.x * blockDim.x + threadIdx.x;
    if (i < PDIM * EMB)
        g_W[i] = __float2bfloat16_rn(__ldg(&proj_w[i]));
}

// ------------------------------------------------ K1: pool (identical to R5/R12)
__global__ void __launch_bounds__(256)
pool_kernel(const int* __restrict__ croutes,
            const float* __restrict__ cid_emb,
            const float* __restrict__ weight,
            const float* __restrict__ content_table,
            const float* __restrict__ proj_w,
            const float* __restrict__ proj_b,
            float* __restrict__ out,
            int npos)
{
    const int pos = blockIdx.x;
    const int t   = threadIdx.x;

    if (blockIdx.x < WCONV_BLOCKS) {
        int i = blockIdx.x * 256 + t;
        g_W[i] = __float2bfloat16_rn(__ldg(&proj_w[i]));
    }
    if (pos >= npos) return;

    __shared__ int   rels[KLEV];
    __shared__ float alph[KLEV];

    if (t < KLEV)
        rels[t] = croutes[(size_t)pos * KLEV + t] + 2;
    __syncthreads();

    if (t == 0) {
        float nw[KLEV];
        float m = -CUDART_INF_F;
#pragma unroll
        for (int k = 0; k < KLEV; k++) {
            nw[k] = (rels[k] != 0) ? __ldg(&weight[k]) : -CUDART_INF_F;
            m = fmaxf(m, nw[k]);
        }
        float s = 0.f, ex[KLEV];
#pragma unroll
        for (int k = 0; k < KLEV; k++) { ex[k] = expf(nw[k] - m); s += ex[k]; }
        float inv = 1.f / s;
#pragma unroll
        for (int k = 0; k < KLEV; k++) alph[k] = ex[k] * inv;
    }
    __syncthreads();

    float a[KLEV]; int r[KLEV];
#pragma unroll
    for (int k = 0; k < KLEV; k++) { a[k] = alph[k]; r[k] = rels[k]; }

    if (t < 192) {
        float4 s = make_float4(0.f, 0.f, 0.f, 0.f);
#pragma unroll
        for (int k = 0; k < KLEV; k++) {
            if (a[k] != 0.f) {
                float4 v = __ldg(((const float4*)content_table) + (size_t)r[k] * 192 + t);
                s.x = fmaf(a[k], v.x, s.x);
                s.y = fmaf(a[k], v.y, s.y);
                s.z = fmaf(a[k], v.z, s.z);
                s.w = fmaf(a[k], v.w, s.w);
            }
        }
        __nv_bfloat162 lo = __floats2bfloat162_rn(s.x, s.y);
        __nv_bfloat162 hi = __floats2bfloat162_rn(s.z, s.w);
        uint2 pk;
        pk.x = *reinterpret_cast<uint32_t*>(&lo);
        pk.y = *reinterpret_cast<uint32_t*>(&hi);
        *reinterpret_cast<uint2*>(g_P + (size_t)pos * PDIM + 4 * t) = pk;
    } else {
        int u = t - 192;
        float4 s = __ldg(((const float4*)proj_b) + u);
#pragma unroll
        for (int k = 0; k < KLEV; k++) {
            if (a[k] != 0.f && r[k] >= 2) {
                float4 v = __ldg(((const float4*)cid_emb) + (size_t)(r[k] - 2) * 64 + u);
                s.x = fmaf(a[k], v.x, s.x);
                s.y = fmaf(a[k], v.y, s.y);
                s.z = fmaf(a[k], v.z, s.z);
                s.w = fmaf(a[k], v.w, s.w);
            }
        }
        *reinterpret_cast<float4*>(out + (size_t)pos * EMB + 4 * u) = s;
    }
}

// ------------------------------------------------ K2: GEMM v10 (single barrier/chunk)
// block (bx, by): rows [64bx,64bx+64), cols [128by, 128by+128)
// 8 warps = 2(M) x 4(N): wm = warp&1 (32 rows), wn = warp>>1 (32 cols)
__global__ void __launch_bounds__(256, 3)
gemm_kernel(float* __restrict__ out, int npos)
{
    extern __shared__ __align__(16) char smem[];

    const int t    = threadIdx.x;
    const int warp = t >> 5;
    const int lane = t & 31;
    const int wm   = warp & 1;
    const int wn   = warp >> 1;
    const int blockRow = blockIdx.x * BM;
    const int nbase    = blockIdx.y * BN;

    float c[2][4][4];
#pragma unroll
    for (int mf = 0; mf < 2; mf++)
#pragma unroll
        for (int nf = 0; nf < 4; nf++)
#pragma unroll
            for (int i = 0; i < 4; i++) c[mf][nf][i] = 0.f;

    // A: 64 rows x 8 chunks of 16B = 512; 2 per thread (u = t, t+256)
    const int a_row0 = t >> 3,         a_ch0 = t & 7;
    const int a_row1 = (t + 256) >> 3, a_ch1 = t & 7;
    int gr0 = blockRow + a_row0; if (gr0 >= npos) gr0 = npos - 1;
    int gr1 = blockRow + a_row1; if (gr1 >= npos) gr1 = npos - 1;
    const __nv_bfloat16* a_src0 = g_P + (size_t)gr0 * PDIM + a_ch0 * 8;
    const __nv_bfloat16* a_src1 = g_P + (size_t)gr1 * PDIM + a_ch1 * 8;
    const uint32_t a_off0 = a_row0 * 128 + ((a_ch0 ^ (a_row0 & 7)) * 16);
    const uint32_t a_off1 = a_row1 * 128 + ((a_ch1 ^ (a_row1 & 7)) * 16);

    auto load_chunk = [&](int kc, int stg) {
        char* base = smem + stg * STG_B;
        cp_async16(smem_u32(base + a_off0), a_src0 + kc * BK);
        cp_async16(smem_u32(base + a_off1), a_src1 + kc * BK);
        char* Wb = base + A_STG_B;
        // W: 64 rows x 16 chunks of 16B = 1024; 4 per thread
#pragma unroll
        for (int i = 0; i < 4; i++) {
            int u  = t + i * 256;             // 0..1023
            int wr = u >> 4, wc = u & 15;     // row 0..63, chunk 0..15
            cp_async16(smem_u32(Wb + wr * 256 + ((wc ^ (wr & 7)) * 16)),
                       g_W + (size_t)(kc * BK + wr) * EMB + nbase + wc * 8);
        }
        cp_commit();
    };

    // prologue: chunks 0,1 into stages 0,1 (chunk 2 issued inside iter 0)
    load_chunk(0, 0);
    load_chunk(1, 1);

    for (int kc = 0; kc < NCHUNK; kc++) {
        // outstanding before wait: chunks kc, kc+1 (if issued). Need kc done.
        if (kc + 1 < NCHUNK) cp_wait<1>(); else cp_wait<0>();
        __syncthreads();   // also proves all warps finished compute(kc-1)

        // refill stage ((kc-1+NSTAGE)%NSTAGE) = stage of chunk kc-1 (vacated)
        if (kc + 2 < NCHUNK)
            load_chunk(kc + 2, (kc + 2) % NSTAGE);

        const char* As = smem + (kc % NSTAGE) * STG_B;
        const char* Ws = As + A_STG_B;

#pragma unroll
        for (int ks = 0; ks < BK / 16; ks++) {
            uint32_t a[2][4];
#pragma unroll
            for (int mf = 0; mf < 2; mf++) {
                int row = wm * 32 + mf * 16 + (lane & 15);
                int ch  = ks * 2 + (lane >> 4);
                uint32_t addr = smem_u32(As + row * 128 + ((ch ^ (row & 7)) * 16));
                asm volatile("ldmatrix.sync.aligned.m8n8.x4.shared.b16 {%0,%1,%2,%3}, [%4];\n"
                             : "=r"(a[mf][0]), "=r"(a[mf][1]), "=r"(a[mf][2]), "=r"(a[mf][3])
                             : "r"(addr));
            }
            uint32_t b[4][2];
#pragma unroll
            for (int nf = 0; nf < 4; nf++) {
                int row = ks * 16 + (lane & 15);
                int ch  = wn * 4 + nf;        // 16B chunk = 8 bf16 cols
                uint32_t addr = smem_u32(Ws + row * 256 + ((ch ^ (row & 7)) * 16));
                asm volatile("ldmatrix.sync.aligned.m8n8.x2.trans.shared.b16 {%0,%1}, [%2];\n"
                             : "=r"(b[nf][0]), "=r"(b[nf][1]) : "r"(addr));
            }
#pragma unroll
            for (int mf = 0; mf < 2; mf++)
#pragma unroll
                for (int nf = 0; nf < 4; nf++) {
                    asm volatile(
                        "mma.sync.aligned.m16n8k16.row.col.f32.bf16.bf16.f32 "
                        "{%0,%1,%2,%3}, {%4,%5,%6,%7}, {%8,%9}, {%0,%1,%2,%3};\n"
                        : "+f"(c[mf][nf][0]), "+f"(c[mf][nf][1]),
                          "+f"(c[mf][nf][2]), "+f"(c[mf][nf][3])
                        : "r"(a[mf][0]), "r"(a[mf][1]), "r"(a[mf][2]), "r"(a[mf][3]),
                          "r"(b[nf][0]), "r"(b[nf][1]));
                }
        }
        // no post-compute barrier: next iteration's wait+syncthreads protects
        // the vacated stage before it is refilled.
    }

    // epilogue: out += C
#pragma unroll
    for (int mf = 0; mf < 2; mf++) {
#pragma unroll
        for (int nf = 0; nf < 4; nf++) {
            int col  = nbase + wn * 32 + nf * 8 + (lane & 3) * 2;
            int row0 = blockRow + wm * 32 + mf * 16 + (lane >> 2);
            if (row0 < npos) {
                float2* o = reinterpret_cast<float2*>(&out[(size_t)row0 * EMB + col]);
                float2 v = *o;
                v.x += c[mf][nf][0]; v.y += c[mf][nf][1];
                *o = v;
            }
            int row1 = row0 + 8;
            if (row1 < npos) {
                float2* o = reinterpret_cast<float2*>(&out[(size_t)row1 * EMB + col]);
                float2 v = *o;
                v.x += c[mf][nf][2]; v.y += c[mf][nf][3];
                *o = v;
            }
        }
    }
}

// ------------------------------------------------ launch
extern "C" void kernel_launch(void* const* d_in, const int* in_sizes, int n_in,
                              void* d_out, int out_size)
{
    const int*   croutes       = (const int*)d_in[0];
    // d_in[1] = tailcs (unused)
    const float* cid_emb       = (const float*)d_in[2];
    const float* weight        = (const float*)d_in[3];
    const float* content_table = (const float*)d_in[4];
    const float* proj_w        = (const float*)d_in[5];
    const float* proj_b        = (const float*)d_in[6];
    float*       out           = (float*)d_out;

    int npos = in_sizes[0] / KLEV;
    if (npos > MAXPOS) npos = MAXPOS;

    if (npos < WCONV_BLOCKS)
        convert_w_kernel<<<(PDIM * EMB + 255) / 256, 256>>>(proj_w);

    pool_kernel<<<npos, 256>>>(croutes, cid_emb, weight, content_table,
                               proj_w, proj_b, out, npos);

    static bool attr_set = false;
    if (!attr_set) {
        cudaFuncSetAttribute(gemm_kernel,
                             cudaFuncAttributeMaxDynamicSharedMemorySize,
                             SMEM_TOTAL);
        attr_set = true;
    }
    dim3 grid((npos + BM - 1) / BM, 2);
    gemm_kernel<<<grid, 256, SMEM_TOTAL>>>(out, npos);
}